// round 11
// baseline (speedup 1.0000x reference)
#include <cuda_runtime.h>
#include <cuda_fp16.h>

#define N_NODES 100000
#define N_EDGES 1000000
#define D_FEAT  64

// Neighbor-sum accumulator. Zero-initialized at module load; k_mlp re-zeroes
// its tile after consuming, so every graph replay sees zeros (deterministic).
__device__ float g_agg[N_NODES * D_FEAT];
// fp16 copy of X, rebuilt every call by k_half (deterministic).
__device__ __half g_xh[N_NODES * D_FEAT];

// ---------------------------------------------------------------------------
// k_half: X (fp32) -> g_xh (fp16). 25.6MB read + 12.8MB write.
// ---------------------------------------------------------------------------
__global__ void k_half(const float4* __restrict__ X4, uint2* __restrict__ xh2,
                       int n4) {
    int i = blockIdx.x * blockDim.x + threadIdx.x;
    if (i < n4) {
        float4 v = __ldg(&X4[i]);
        __half2 a = __floats2half2_rn(v.x, v.y);
        __half2 b = __floats2half2_rn(v.z, v.w);
        xh2[i] = make_uint2(*(unsigned*)&a, *(unsigned*)&b);
    }
}

// ---------------------------------------------------------------------------
// Edge scatter: 8 threads per edge; each reads a 16B fp16 chunk (8 cols) of
// the neighbor row, converts, and REDs fp32 into agg — both directions.
// Read bytes through LTS halved vs fp32 rows; RED traffic unchanged.
// ---------------------------------------------------------------------------
__device__ __forceinline__ void red_add_v4(float* addr, float4 v) {
    asm volatile("red.global.add.v4.f32 [%0], {%1, %2, %3, %4};"
                 :: "l"(addr), "f"(v.x), "f"(v.y), "f"(v.z), "f"(v.w)
                 : "memory");
}

__device__ __forceinline__ void red_row8(float* dst, uint4 h) {
    float2 f0 = __half22float2(*(__half2*)&h.x);
    float2 f1 = __half22float2(*(__half2*)&h.y);
    float2 f2 = __half22float2(*(__half2*)&h.z);
    float2 f3 = __half22float2(*(__half2*)&h.w);
    red_add_v4(dst,     make_float4(f0.x, f0.y, f1.x, f1.y));
    red_add_v4(dst + 4, make_float4(f2.x, f2.y, f3.x, f3.y));
}

__global__ void k_scatter(const uint4* __restrict__ Xh4,
                          const int* __restrict__ ref_a,
                          const int* __restrict__ ref_b) {
    unsigned t = blockIdx.x * blockDim.x + threadIdx.x;
    unsigned e = t >> 3;
    unsigned c = t & 7;          // 8 chunks of 8 cols (16B fp16 each)
    if (e >= N_EDGES) return;
    int a = __ldg(&ref_a[e]);
    int b = __ldg(&ref_b[e]);
    uint4 hb = __ldg(&Xh4[(size_t)b * 8 + c]);
    uint4 ha = __ldg(&Xh4[(size_t)a * 8 + c]);
    red_row8(&g_agg[(size_t)a * 64 + 8 * c], hb);
    red_row8(&g_agg[(size_t)b * 64 + 8 * c], ha);
}

// ---------------------------------------------------------------------------
// FP16 m16n8k16 register-fragment MLP (fp32 accumulate), warp-private staging:
//   out = relu(relu((X+agg) @ Wh + bh) @ Wo + bo)
// (identical to round-10 passing kernel except ingress reads Xh fp16)
// ---------------------------------------------------------------------------
#define TSW 72                                  // Ts row stride in 32-bit words
#define MLP_SMEM ((4096 + 128 * TSW) * 4)       // Wp 16KB + Ts 36KB = 52.0KB

__device__ __forceinline__ unsigned h2(float lo, float hi) {
    __half2 h = __floats2half2_rn(lo, hi);
    return *(unsigned*)&h;
}

__device__ __forceinline__ void mma_f16(float* d, unsigned a0, unsigned a1,
                                        unsigned a2, unsigned a3,
                                        unsigned b0, unsigned b1) {
    asm volatile(
        "mma.sync.aligned.m16n8k16.row.col.f32.f16.f16.f32 "
        "{%0,%1,%2,%3}, {%4,%5,%6,%7}, {%8,%9}, {%0,%1,%2,%3};\n"
        : "+f"(d[0]), "+f"(d[1]), "+f"(d[2]), "+f"(d[3])
        : "r"(a0), "r"(a1), "r"(a2), "r"(a3), "r"(b0), "r"(b1));
}

__global__ __launch_bounds__(256, 3)
void k_mlp(float4* agg4,                        // read + zeroed (NOT restrict)
           const uint2* __restrict__ Xh2,
           const float* __restrict__ Wh_g, const float* __restrict__ bh,
           const float* __restrict__ Wo_g, const float* __restrict__ bo,
           float4* __restrict__ out4) {
    extern __shared__ unsigned sm[];
    unsigned* Wp = sm;              // [2][2048] packed fp16 weight fragments
    unsigned* Ts = sm + 4096;       // [128][TSW] warp-private staging

    const int tid  = threadIdx.x;
    const int lane = tid & 31;
    const int warp = tid >> 5;
    const int g    = lane >> 2;      // 0..7
    const int tg   = lane & 3;       // 0..3
    const int row0 = blockIdx.x * 128;

    // ---- Stage weights: slot (l, s, np, lane), 4 words per slot ----
    #pragma unroll
    for (int l = 0; l < 2; l++) {
        const float* W = l ? Wo_g : Wh_g;
        #pragma unroll
        for (int ii = 0; ii < 2; ii++) {
            int i = tid + ii * 256;          // 0..511 slots
            int ln = i & 31;
            int np = (i >> 5) & 3;
            int s  = i >> 7;                 // 0..3
            int tgg = ln & 3, gg = ln >> 2;
            int n0 = 16 * np + gg;
            int n1 = n0 + 8;
            unsigned* dst = &Wp[l * 2048 + i * 4];
            if (l == 0) {
                int r = 16 * tgg + 4 * s;
                dst[0] = h2(__ldg(&W[r * 64 + n0]),       __ldg(&W[(r + 1) * 64 + n0]));
                dst[1] = h2(__ldg(&W[(r + 2) * 64 + n0]), __ldg(&W[(r + 3) * 64 + n0]));
                dst[2] = h2(__ldg(&W[r * 64 + n1]),       __ldg(&W[(r + 1) * 64 + n1]));
                dst[3] = h2(__ldg(&W[(r + 2) * 64 + n1]), __ldg(&W[(r + 3) * 64 + n1]));
            } else {
                int ra = 16 * s + 2 * tgg;
                int rb = ra + 8;
                dst[0] = h2(__ldg(&W[ra * 64 + n0]), __ldg(&W[(ra + 1) * 64 + n0]));
                dst[1] = h2(__ldg(&W[rb * 64 + n0]), __ldg(&W[(rb + 1) * 64 + n0]));
                dst[2] = h2(__ldg(&W[ra * 64 + n1]), __ldg(&W[(ra + 1) * 64 + n1]));
                dst[3] = h2(__ldg(&W[rb * 64 + n1]), __ldg(&W[(rb + 1) * 64 + n1]));
            }
        }
    }
    __syncthreads();   // the only block barrier

    // ---- Per-warp coalesced ingress: own 16 rows of half2(Xh + agg) ----
    #pragma unroll
    for (int i = 0; i < 8; i++) {
        int idx = i * 32 + lane;             // 0..255 float4 within warp tile
        int r  = warp * 16 + (idx >> 4);     // local row (warp-private)
        int c4 = idx & 15;
        int grow = row0 + r;
        uint2 st = make_uint2(0u, 0u);
        if (grow < N_NODES) {
            float4 a = agg4[(size_t)grow * 16 + c4];
            uint2 xh = __ldg(&Xh2[(size_t)grow * 16 + c4]);
            float2 f0 = __half22float2(*(__half2*)&xh.x);
            float2 f1 = __half22float2(*(__half2*)&xh.y);
            st.x = h2(a.x + f0.x, a.y + f0.y);
            st.y = h2(a.z + f1.x, a.w + f1.y);
        }
        *(uint2*)&Ts[r * TSW + c4 * 2] = st;
    }

    // Compiler barrier: agg loads above must materialize before the zeroing
    // stores below (same buffer!).
    asm volatile("" ::: "memory");

    // Re-zero own agg rows (fire-and-forget coalesced stores).
    {
        const float4 z4 = make_float4(0.f, 0.f, 0.f, 0.f);
        #pragma unroll
        for (int i = 0; i < 8; i++) {
            int idx = i * 32 + lane;
            int grow = row0 + warp * 16 + (idx >> 4);
            if (grow < N_NODES)
                agg4[(size_t)grow * 16 + (idx & 15)] = z4;
        }
    }
    __syncwarp();

    // ---- Pull A fragments: words [8tg, 8tg+8) of own two rows ----
    const int lr0 = warp * 16 + g;
    const int lr1 = lr0 + 8;
    unsigned w0[8], w1[8];           // [m] = phys cols (16tg+2m, 16tg+2m+1)
    *(uint4*)&w0[0] = *(const uint4*)&Ts[lr0 * TSW + 8 * tg];
    *(uint4*)&w0[4] = *(const uint4*)&Ts[lr0 * TSW + 8 * tg + 4];
    *(uint4*)&w1[0] = *(const uint4*)&Ts[lr1 * TSW + 8 * tg];
    *(uint4*)&w1[4] = *(const uint4*)&Ts[lr1 * TSW + 8 * tg + 4];

    // ================= Layer 1 =================
    float acc[8][4];
    #pragma unroll
    for (int nt = 0; nt < 8; nt++) {
        float blo = __ldg(&bh[nt * 8 + 2 * tg]);
        float bhi = __ldg(&bh[nt * 8 + 2 * tg + 1]);
        acc[nt][0] = blo; acc[nt][1] = bhi; acc[nt][2] = blo; acc[nt][3] = bhi;
    }
    #pragma unroll
    for (int s = 0; s < 4; s++) {
        unsigned A0 = w0[2 * s],     A1 = w1[2 * s];
        unsigned A2 = w0[2 * s + 1], A3 = w1[2 * s + 1];
        #pragma unroll
        for (int np = 0; np < 4; np++) {
            uint4 b = *(const uint4*)&Wp[((s * 4 + np) * 32 + lane) * 4];
            mma_f16(acc[2 * np],     A0, A1, A2, A3, b.x, b.y);
            mma_f16(acc[2 * np + 1], A0, A1, A2, A3, b.z, b.w);
        }
    }

    // ---- relu + pack: accumulators become layer-2 A fragments directly ----
    unsigned ha0[4], ha1[4], ha2[4], ha3[4];
    #pragma unroll
    for (int s = 0; s < 4; s++) {
        ha0[s] = h2(fmaxf(acc[2 * s][0], 0.f),     fmaxf(acc[2 * s][1], 0.f));
        ha1[s] = h2(fmaxf(acc[2 * s][2], 0.f),     fmaxf(acc[2 * s][3], 0.f));
        ha2[s] = h2(fmaxf(acc[2 * s + 1][0], 0.f), fmaxf(acc[2 * s + 1][1], 0.f));
        ha3[s] = h2(fmaxf(acc[2 * s + 1][2], 0.f), fmaxf(acc[2 * s + 1][3], 0.f));
    }

    // ================= Layer 2 =================
    #pragma unroll
    for (int nt = 0; nt < 8; nt++) {
        float blo = __ldg(&bo[nt * 8 + 2 * tg]);
        float bhi = __ldg(&bo[nt * 8 + 2 * tg + 1]);
        acc[nt][0] = blo; acc[nt][1] = bhi; acc[nt][2] = blo; acc[nt][3] = bhi;
    }
    #pragma unroll
    for (int s = 0; s < 4; s++) {
        #pragma unroll
        for (int np = 0; np < 4; np++) {
            uint4 b = *(const uint4*)&Wp[2048 + ((s * 4 + np) * 32 + lane) * 4];
            mma_f16(acc[2 * np],     ha0[s], ha1[s], ha2[s], ha3[s], b.x, b.y);
            mma_f16(acc[2 * np + 1], ha0[s], ha1[s], ha2[s], ha3[s], b.z, b.w);
        }
    }

    // ---- Egress: relu -> own warp stripe as fp32 (warp-private) ----
    __syncwarp();
    #pragma unroll
    for (int nt = 0; nt < 8; nt++) {
        int c = nt * 8 + 2 * tg;
        *(uint2*)&Ts[lr0 * TSW + c] = make_uint2(
            __float_as_uint(fmaxf(acc[nt][0], 0.f)),
            __float_as_uint(fmaxf(acc[nt][1], 0.f)));
        *(uint2*)&Ts[lr1 * TSW + c] = make_uint2(
            __float_as_uint(fmaxf(acc[nt][2], 0.f)),
            __float_as_uint(fmaxf(acc[nt][3], 0.f)));
    }
    __syncwarp();

    // ---- Per-warp coalesced STG.128 of own 16 output rows ----
    #pragma unroll
    for (int i = 0; i < 8; i++) {
        int idx = i * 32 + lane;
        int r  = warp * 16 + (idx >> 4);
        int c4 = idx & 15;
        int grow = row0 + r;
        if (grow < N_NODES) {
            uint4 v = *(const uint4*)&Ts[r * TSW + c4 * 4];
            out4[(size_t)grow * 16 + c4] = make_float4(
                __uint_as_float(v.x), __uint_as_float(v.y),
                __uint_as_float(v.z), __uint_as_float(v.w));
        }
    }
}

// ---------------------------------------------------------------------------
// Inputs: 0=X, 1=ref_a, 2=ref_b, 3=v_map(unused), 4=v_count(unused),
//         5=W_hidden, 6=b_hidden, 7=W_out, 8=b_out
// ---------------------------------------------------------------------------
extern "C" void kernel_launch(void* const* d_in, const int* in_sizes, int n_in,
                              void* d_out, int out_size) {
    const float* X   = (const float*)d_in[0];
    const int* ref_a = (const int*)d_in[1];
    const int* ref_b = (const int*)d_in[2];
    const float* Wh  = (const float*)d_in[5];
    const float* bh  = (const float*)d_in[6];
    const float* Wo  = (const float*)d_in[7];
    const float* bo  = (const float*)d_in[8];
    float* out = (float*)d_out;

    float* agg;
    cudaGetSymbolAddress((void**)&agg, g_agg);
    __half* xh;
    cudaGetSymbolAddress((void**)&xh, g_xh);

    // 1) fp16 copy of X
    {
        int n4 = N_NODES * D_FEAT / 4;   // 1.6M float4
        k_half<<<(n4 + 255) / 256, 256>>>((const float4*)X, (uint2*)xh, n4);
    }

    // 2) edge scatter (fp16 reads, fp32 RED accumulate)
    {
        long long total = (long long)N_EDGES * 8;
        int blocks = (int)((total + 255) / 256);
        k_scatter<<<blocks, 256>>>((const uint4*)xh, ref_a, ref_b);
    }

    // 3) FP16 register-fragment MLP (adds Xh, consumes agg, re-zeroes agg)
    {
        cudaFuncSetAttribute(k_mlp, cudaFuncAttributeMaxDynamicSharedMemorySize,
                             MLP_SMEM);
        int blocks = (N_NODES + 127) / 128;   // 782
        k_mlp<<<blocks, 256, MLP_SMEM>>>((float4*)agg, (const uint2*)xh,
                                         Wh, bh, Wo, bo, (float4*)out);
    }
}

// round 12
// speedup vs baseline: 1.3501x; 1.3501x over previous
#include <cuda_runtime.h>
#include <cuda_fp16.h>

#define N_NODES 100000
#define N_EDGES 1000000
#define D_FEAT  64

// Neighbor-sum accumulator. Zero-initialized at module load; k_mlp re-zeroes
// its tile after consuming, so every graph replay sees zeros (deterministic).
__device__ float g_agg[N_NODES * D_FEAT];
// fp16 copy of X, rebuilt every call by k_half (deterministic).
__device__ __half g_xh[N_NODES * D_FEAT];

// ---------------------------------------------------------------------------
// k_half: X (fp32) -> g_xh (fp16). 25.6MB read + 12.8MB write. ~8.6us.
// ---------------------------------------------------------------------------
__global__ void k_half(const float4* __restrict__ X4, uint2* __restrict__ xh2,
                       int n4) {
    int i = blockIdx.x * blockDim.x + threadIdx.x;
    if (i < n4) {
        float4 v = __ldg(&X4[i]);
        __half2 a = __floats2half2_rn(v.x, v.y);
        __half2 b = __floats2half2_rn(v.z, v.w);
        xh2[i] = make_uint2(*(unsigned*)&a, *(unsigned*)&b);
    }
}

// ---------------------------------------------------------------------------
// Edge scatter — round-10 geometry (16 threads/edge, ONE red.v4 per direction
// per thread), but neighbor rows read as fp16 (uint2 = 4 cols) to halve the
// LTS read bytes. RED pattern/addressing identical to the known-good kernel.
// ---------------------------------------------------------------------------
__device__ __forceinline__ void red_add_v4(float* addr, float4 v) {
    asm volatile("red.global.add.v4.f32 [%0], {%1, %2, %3, %4};"
                 :: "l"(addr), "f"(v.x), "f"(v.y), "f"(v.z), "f"(v.w)
                 : "memory");
}

__device__ __forceinline__ float4 cvt4(uint2 h) {
    float2 f0 = __half22float2(*(__half2*)&h.x);
    float2 f1 = __half22float2(*(__half2*)&h.y);
    return make_float4(f0.x, f0.y, f1.x, f1.y);
}

__global__ void k_scatter(const uint2* __restrict__ Xh2,
                          const int* __restrict__ ref_a,
                          const int* __restrict__ ref_b) {
    unsigned t = blockIdx.x * blockDim.x + threadIdx.x;
    unsigned e = t >> 4;
    unsigned c = t & 15;         // 16 chunks of 4 cols each
    if (e >= N_EDGES) return;
    int a = __ldg(&ref_a[e]);
    int b = __ldg(&ref_b[e]);
    uint2 hb = __ldg(&Xh2[(size_t)b * 16 + c]);
    uint2 ha = __ldg(&Xh2[(size_t)a * 16 + c]);
    red_add_v4(&g_agg[(size_t)a * 64 + 4 * c], cvt4(hb));
    red_add_v4(&g_agg[(size_t)b * 64 + 4 * c], cvt4(ha));
}

// ---------------------------------------------------------------------------
// FP16 m16n8k16 register-fragment MLP (fp32 accumulate), warp-private staging:
//   out = relu(relu((X+agg) @ Wh + bh) @ Wo + bo)
// (unchanged from the round-10/11 passing kernel; ingress reads Xh fp16)
// ---------------------------------------------------------------------------
#define TSW 72                                  // Ts row stride in 32-bit words
#define MLP_SMEM ((4096 + 128 * TSW) * 4)       // Wp 16KB + Ts 36KB = 52.0KB

__device__ __forceinline__ unsigned h2(float lo, float hi) {
    __half2 h = __floats2half2_rn(lo, hi);
    return *(unsigned*)&h;
}

__device__ __forceinline__ void mma_f16(float* d, unsigned a0, unsigned a1,
                                        unsigned a2, unsigned a3,
                                        unsigned b0, unsigned b1) {
    asm volatile(
        "mma.sync.aligned.m16n8k16.row.col.f32.f16.f16.f32 "
        "{%0,%1,%2,%3}, {%4,%5,%6,%7}, {%8,%9}, {%0,%1,%2,%3};\n"
        : "+f"(d[0]), "+f"(d[1]), "+f"(d[2]), "+f"(d[3])
        : "r"(a0), "r"(a1), "r"(a2), "r"(a3), "r"(b0), "r"(b1));
}

__global__ __launch_bounds__(256, 3)
void k_mlp(float4* agg4,                        // read + zeroed (NOT restrict)
           const uint2* __restrict__ Xh2,
           const float* __restrict__ Wh_g, const float* __restrict__ bh,
           const float* __restrict__ Wo_g, const float* __restrict__ bo,
           float4* __restrict__ out4) {
    extern __shared__ unsigned sm[];
    unsigned* Wp = sm;              // [2][2048] packed fp16 weight fragments
    unsigned* Ts = sm + 4096;       // [128][TSW] warp-private staging

    const int tid  = threadIdx.x;
    const int lane = tid & 31;
    const int warp = tid >> 5;
    const int g    = lane >> 2;      // 0..7
    const int tg   = lane & 3;       // 0..3
    const int row0 = blockIdx.x * 128;

    // ---- Stage weights: slot (l, s, np, lane), 4 words per slot ----
    #pragma unroll
    for (int l = 0; l < 2; l++) {
        const float* W = l ? Wo_g : Wh_g;
        #pragma unroll
        for (int ii = 0; ii < 2; ii++) {
            int i = tid + ii * 256;          // 0..511 slots
            int ln = i & 31;
            int np = (i >> 5) & 3;
            int s  = i >> 7;                 // 0..3
            int tgg = ln & 3, gg = ln >> 2;
            int n0 = 16 * np + gg;
            int n1 = n0 + 8;
            unsigned* dst = &Wp[l * 2048 + i * 4];
            if (l == 0) {
                int r = 16 * tgg + 4 * s;
                dst[0] = h2(__ldg(&W[r * 64 + n0]),       __ldg(&W[(r + 1) * 64 + n0]));
                dst[1] = h2(__ldg(&W[(r + 2) * 64 + n0]), __ldg(&W[(r + 3) * 64 + n0]));
                dst[2] = h2(__ldg(&W[r * 64 + n1]),       __ldg(&W[(r + 1) * 64 + n1]));
                dst[3] = h2(__ldg(&W[(r + 2) * 64 + n1]), __ldg(&W[(r + 3) * 64 + n1]));
            } else {
                int ra = 16 * s + 2 * tgg;
                int rb = ra + 8;
                dst[0] = h2(__ldg(&W[ra * 64 + n0]), __ldg(&W[(ra + 1) * 64 + n0]));
                dst[1] = h2(__ldg(&W[rb * 64 + n0]), __ldg(&W[(rb + 1) * 64 + n0]));
                dst[2] = h2(__ldg(&W[ra * 64 + n1]), __ldg(&W[(ra + 1) * 64 + n1]));
                dst[3] = h2(__ldg(&W[rb * 64 + n1]), __ldg(&W[(rb + 1) * 64 + n1]));
            }
        }
    }
    __syncthreads();   // the only block barrier

    // ---- Per-warp coalesced ingress: own 16 rows of half2(Xh + agg) ----
    #pragma unroll
    for (int i = 0; i < 8; i++) {
        int idx = i * 32 + lane;             // 0..255 float4 within warp tile
        int r  = warp * 16 + (idx >> 4);     // local row (warp-private)
        int c4 = idx & 15;
        int grow = row0 + r;
        uint2 st = make_uint2(0u, 0u);
        if (grow < N_NODES) {
            float4 a = agg4[(size_t)grow * 16 + c4];
            uint2 xh = __ldg(&Xh2[(size_t)grow * 16 + c4]);
            float2 f0 = __half22float2(*(__half2*)&xh.x);
            float2 f1 = __half22float2(*(__half2*)&xh.y);
            st.x = h2(a.x + f0.x, a.y + f0.y);
            st.y = h2(a.z + f1.x, a.w + f1.y);
        }
        *(uint2*)&Ts[r * TSW + c4 * 2] = st;
    }

    // Compiler barrier: agg loads above must materialize before the zeroing
    // stores below (same buffer!).
    asm volatile("" ::: "memory");

    // Re-zero own agg rows (fire-and-forget coalesced stores).
    {
        const float4 z4 = make_float4(0.f, 0.f, 0.f, 0.f);
        #pragma unroll
        for (int i = 0; i < 8; i++) {
            int idx = i * 32 + lane;
            int grow = row0 + warp * 16 + (idx >> 4);
            if (grow < N_NODES)
                agg4[(size_t)grow * 16 + (idx & 15)] = z4;
        }
    }
    __syncwarp();

    // ---- Pull A fragments: words [8tg, 8tg+8) of own two rows ----
    const int lr0 = warp * 16 + g;
    const int lr1 = lr0 + 8;
    unsigned w0[8], w1[8];           // [m] = phys cols (16tg+2m, 16tg+2m+1)
    *(uint4*)&w0[0] = *(const uint4*)&Ts[lr0 * TSW + 8 * tg];
    *(uint4*)&w0[4] = *(const uint4*)&Ts[lr0 * TSW + 8 * tg + 4];
    *(uint4*)&w1[0] = *(const uint4*)&Ts[lr1 * TSW + 8 * tg];
    *(uint4*)&w1[4] = *(const uint4*)&Ts[lr1 * TSW + 8 * tg + 4];

    // ================= Layer 1 =================
    float acc[8][4];
    #pragma unroll
    for (int nt = 0; nt < 8; nt++) {
        float blo = __ldg(&bh[nt * 8 + 2 * tg]);
        float bhi = __ldg(&bh[nt * 8 + 2 * tg + 1]);
        acc[nt][0] = blo; acc[nt][1] = bhi; acc[nt][2] = blo; acc[nt][3] = bhi;
    }
    #pragma unroll
    for (int s = 0; s < 4; s++) {
        unsigned A0 = w0[2 * s],     A1 = w1[2 * s];
        unsigned A2 = w0[2 * s + 1], A3 = w1[2 * s + 1];
        #pragma unroll
        for (int np = 0; np < 4; np++) {
            uint4 b = *(const uint4*)&Wp[((s * 4 + np) * 32 + lane) * 4];
            mma_f16(acc[2 * np],     A0, A1, A2, A3, b.x, b.y);
            mma_f16(acc[2 * np + 1], A0, A1, A2, A3, b.z, b.w);
        }
    }

    // ---- relu + pack: accumulators become layer-2 A fragments directly ----
    unsigned ha0[4], ha1[4], ha2[4], ha3[4];
    #pragma unroll
    for (int s = 0; s < 4; s++) {
        ha0[s] = h2(fmaxf(acc[2 * s][0], 0.f),     fmaxf(acc[2 * s][1], 0.f));
        ha1[s] = h2(fmaxf(acc[2 * s][2], 0.f),     fmaxf(acc[2 * s][3], 0.f));
        ha2[s] = h2(fmaxf(acc[2 * s + 1][0], 0.f), fmaxf(acc[2 * s + 1][1], 0.f));
        ha3[s] = h2(fmaxf(acc[2 * s + 1][2], 0.f), fmaxf(acc[2 * s + 1][3], 0.f));
    }

    // ================= Layer 2 =================
    #pragma unroll
    for (int nt = 0; nt < 8; nt++) {
        float blo = __ldg(&bo[nt * 8 + 2 * tg]);
        float bhi = __ldg(&bo[nt * 8 + 2 * tg + 1]);
        acc[nt][0] = blo; acc[nt][1] = bhi; acc[nt][2] = blo; acc[nt][3] = bhi;
    }
    #pragma unroll
    for (int s = 0; s < 4; s++) {
        #pragma unroll
        for (int np = 0; np < 4; np++) {
            uint4 b = *(const uint4*)&Wp[2048 + ((s * 4 + np) * 32 + lane) * 4];
            mma_f16(acc[2 * np],     ha0[s], ha1[s], ha2[s], ha3[s], b.x, b.y);
            mma_f16(acc[2 * np + 1], ha0[s], ha1[s], ha2[s], ha3[s], b.z, b.w);
        }
    }

    // ---- Egress: relu -> own warp stripe as fp32 (warp-private) ----
    __syncwarp();
    #pragma unroll
    for (int nt = 0; nt < 8; nt++) {
        int c = nt * 8 + 2 * tg;
        *(uint2*)&Ts[lr0 * TSW + c] = make_uint2(
            __float_as_uint(fmaxf(acc[nt][0], 0.f)),
            __float_as_uint(fmaxf(acc[nt][1], 0.f)));
        *(uint2*)&Ts[lr1 * TSW + c] = make_uint2(
            __float_as_uint(fmaxf(acc[nt][2], 0.f)),
            __float_as_uint(fmaxf(acc[nt][3], 0.f)));
    }
    __syncwarp();

    // ---- Per-warp coalesced STG.128 of own 16 output rows ----
    #pragma unroll
    for (int i = 0; i < 8; i++) {
        int idx = i * 32 + lane;
        int r  = warp * 16 + (idx >> 4);
        int c4 = idx & 15;
        int grow = row0 + r;
        if (grow < N_NODES) {
            uint4 v = *(const uint4*)&Ts[r * TSW + c4 * 4];
            out4[(size_t)grow * 16 + c4] = make_float4(
                __uint_as_float(v.x), __uint_as_float(v.y),
                __uint_as_float(v.z), __uint_as_float(v.w));
        }
    }
}

// ---------------------------------------------------------------------------
// Inputs: 0=X, 1=ref_a, 2=ref_b, 3=v_map(unused), 4=v_count(unused),
//         5=W_hidden, 6=b_hidden, 7=W_out, 8=b_out
// ---------------------------------------------------------------------------
extern "C" void kernel_launch(void* const* d_in, const int* in_sizes, int n_in,
                              void* d_out, int out_size) {
    const float* X   = (const float*)d_in[0];
    const int* ref_a = (const int*)d_in[1];
    const int* ref_b = (const int*)d_in[2];
    const float* Wh  = (const float*)d_in[5];
    const float* bh  = (const float*)d_in[6];
    const float* Wo  = (const float*)d_in[7];
    const float* bo  = (const float*)d_in[8];
    float* out = (float*)d_out;

    float* agg;
    cudaGetSymbolAddress((void**)&agg, g_agg);
    __half* xh;
    cudaGetSymbolAddress((void**)&xh, g_xh);

    // 1) fp16 copy of X
    {
        int n4 = N_NODES * D_FEAT / 4;   // 1.6M float4
        k_half<<<(n4 + 255) / 256, 256>>>((const float4*)X, (uint2*)xh, n4);
    }

    // 2) edge scatter (fp16 reads, round-10 RED geometry)
    {
        long long total = (long long)N_EDGES * 16;
        int blocks = (int)((total + 255) / 256);
        k_scatter<<<blocks, 256>>>((const uint2*)xh, ref_a, ref_b);
    }

    // 3) FP16 register-fragment MLP (adds Xh, consumes agg, re-zeroes agg)
    {
        cudaFuncSetAttribute(k_mlp, cudaFuncAttributeMaxDynamicSharedMemorySize,
                             MLP_SMEM);
        int blocks = (N_NODES + 127) / 128;   // 782
        k_mlp<<<blocks, 256, MLP_SMEM>>>((float4*)agg, (const uint2*)xh,
                                         Wh, bh, Wo, bo, (float4*)out);
    }
}

// round 13
// speedup vs baseline: 1.4036x; 1.0396x over previous
#include <cuda_runtime.h>
#include <cuda_fp16.h>

#define N_NODES 100000
#define N_EDGES 1000000
#define D_FEAT  64

#define N_TILES   ((N_NODES + 127) / 128)    // 782
#define GRID_MLP  444                        // 148 SMs x 3 CTAs, persistent

// Neighbor-sum accumulator. Zero-initialized at module load; k_mlp re-zeroes
// its tiles after consuming, so every graph replay sees zeros (deterministic).
__device__ float g_agg[N_NODES * D_FEAT];

// ---------------------------------------------------------------------------
// Edge scatter: 16 threads per edge, one red.v4 per direction per thread.
// Bound by the LTS atomic op rate (~79us) — measured floor for this structure.
// ---------------------------------------------------------------------------
__device__ __forceinline__ void red_add_v4(float* addr, float4 v) {
    asm volatile("red.global.add.v4.f32 [%0], {%1, %2, %3, %4};"
                 :: "l"(addr), "f"(v.x), "f"(v.y), "f"(v.z), "f"(v.w)
                 : "memory");
}

__global__ void k_scatter(const float4* __restrict__ X4,
                          const int* __restrict__ ref_a,
                          const int* __restrict__ ref_b) {
    unsigned t = blockIdx.x * blockDim.x + threadIdx.x;
    unsigned e = t >> 4;
    unsigned c = t & 15;
    if (e >= N_EDGES) return;
    int a = __ldg(&ref_a[e]);
    int b = __ldg(&ref_b[e]);
    const int F4 = D_FEAT / 4;   // 16
    float4 xb = __ldg(&X4[(size_t)b * F4 + c]);
    float4 xa = __ldg(&X4[(size_t)a * F4 + c]);
    red_add_v4(&g_agg[((size_t)a * F4 + c) * 4], xb);
    red_add_v4(&g_agg[((size_t)b * F4 + c) * 4], xa);
}

// ---------------------------------------------------------------------------
// Persistent FP16 m16n8k16 register-fragment MLP (fp32 accumulate):
//   out = relu(relu((X+agg) @ Wh + bh) @ Wo + bo)
// 444 persistent blocks x 256 threads; weights staged ONCE per block, then
// each block loops over tiles row0 = (bid + k*444)*128. All Ts staging is
// warp-private (warp w owns rows [16w,16w+16)) -> no block barrier in loop.
// k-permutation (layer 1) + accumulator->A-fragment chaining (layer 2) as in
// the round-10 passing kernel.
// ---------------------------------------------------------------------------
#define TSW 72                                  // Ts row stride in 32-bit words
#define MLP_SMEM ((4096 + 128 * TSW) * 4)       // Wp 16KB + Ts 36KB = 52.0KB

__device__ __forceinline__ unsigned h2(float lo, float hi) {
    __half2 h = __floats2half2_rn(lo, hi);
    return *(unsigned*)&h;
}

__device__ __forceinline__ void mma_f16(float* d, unsigned a0, unsigned a1,
                                        unsigned a2, unsigned a3,
                                        unsigned b0, unsigned b1) {
    asm volatile(
        "mma.sync.aligned.m16n8k16.row.col.f32.f16.f16.f32 "
        "{%0,%1,%2,%3}, {%4,%5,%6,%7}, {%8,%9}, {%0,%1,%2,%3};\n"
        : "+f"(d[0]), "+f"(d[1]), "+f"(d[2]), "+f"(d[3])
        : "r"(a0), "r"(a1), "r"(a2), "r"(a3), "r"(b0), "r"(b1));
}

__global__ __launch_bounds__(256, 3)
void k_mlp(float4* agg4,                        // read + zeroed (NOT restrict)
           const float4* __restrict__ X4,
           const float* __restrict__ Wh_g, const float* __restrict__ bh,
           const float* __restrict__ Wo_g, const float* __restrict__ bo,
           float4* __restrict__ out4) {
    extern __shared__ unsigned sm[];
    unsigned* Wp = sm;              // [2][2048] packed fp16 weight fragments
    unsigned* Ts = sm + 4096;       // [128][TSW] warp-private staging

    const int tid  = threadIdx.x;
    const int lane = tid & 31;
    const int warp = tid >> 5;
    const int g    = lane >> 2;      // 0..7
    const int tg   = lane & 3;       // 0..3

    // ---- Stage weights ONCE: slot (l, s, np, lane), 4 words per slot ----
    #pragma unroll
    for (int l = 0; l < 2; l++) {
        const float* W = l ? Wo_g : Wh_g;
        #pragma unroll
        for (int ii = 0; ii < 2; ii++) {
            int i = tid + ii * 256;          // 0..511 slots
            int ln = i & 31;
            int np = (i >> 5) & 3;
            int s  = i >> 7;                 // 0..3
            int tgg = ln & 3, gg = ln >> 2;
            int n0 = 16 * np + gg;
            int n1 = n0 + 8;
            unsigned* dst = &Wp[l * 2048 + i * 4];
            if (l == 0) {
                int r = 16 * tgg + 4 * s;
                dst[0] = h2(__ldg(&W[r * 64 + n0]),       __ldg(&W[(r + 1) * 64 + n0]));
                dst[1] = h2(__ldg(&W[(r + 2) * 64 + n0]), __ldg(&W[(r + 3) * 64 + n0]));
                dst[2] = h2(__ldg(&W[r * 64 + n1]),       __ldg(&W[(r + 1) * 64 + n1]));
                dst[3] = h2(__ldg(&W[(r + 2) * 64 + n1]), __ldg(&W[(r + 3) * 64 + n1]));
            } else {
                int ra = 16 * s + 2 * tgg;
                int rb = ra + 8;
                dst[0] = h2(__ldg(&W[ra * 64 + n0]), __ldg(&W[(ra + 1) * 64 + n0]));
                dst[1] = h2(__ldg(&W[rb * 64 + n0]), __ldg(&W[(rb + 1) * 64 + n0]));
                dst[2] = h2(__ldg(&W[ra * 64 + n1]), __ldg(&W[(ra + 1) * 64 + n1]));
                dst[3] = h2(__ldg(&W[rb * 64 + n1]), __ldg(&W[(rb + 1) * 64 + n1]));
            }
        }
    }
    // Bias fragments (constant across tiles) — hoisted out of the tile loop.
    float bh_lo[8], bh_hi[8], bo_lo[8], bo_hi[8];
    #pragma unroll
    for (int nt = 0; nt < 8; nt++) {
        bh_lo[nt] = __ldg(&bh[nt * 8 + 2 * tg]);
        bh_hi[nt] = __ldg(&bh[nt * 8 + 2 * tg + 1]);
        bo_lo[nt] = __ldg(&bo[nt * 8 + 2 * tg]);
        bo_hi[nt] = __ldg(&bo[nt * 8 + 2 * tg + 1]);
    }
    __syncthreads();   // the only block barrier

    const int lr0 = warp * 16 + g;
    const int lr1 = lr0 + 8;

    // ================= Persistent tile loop =================
    for (int tile = blockIdx.x; tile < N_TILES; tile += GRID_MLP) {
        const int row0 = tile * 128;

        // ---- Per-warp coalesced ingress: own 16 rows of half2(X + agg) ----
        #pragma unroll
        for (int i = 0; i < 8; i++) {
            int idx = i * 32 + lane;             // 0..255 float4 in warp tile
            int r  = warp * 16 + (idx >> 4);     // local row (warp-private)
            int c4 = idx & 15;
            int grow = row0 + r;
            uint2 st = make_uint2(0u, 0u);
            if (grow < N_NODES) {
                float4 a = agg4[(size_t)grow * 16 + c4];
                float4 x = __ldg(&X4[(size_t)grow * 16 + c4]);
                st.x = h2(a.x + x.x, a.y + x.y);
                st.y = h2(a.z + x.z, a.w + x.w);
            }
            *(uint2*)&Ts[r * TSW + c4 * 2] = st;
        }

        // Compiler barrier: agg loads above must materialize before the
        // zeroing stores below (same buffer!).
        asm volatile("" ::: "memory");

        // Re-zero own agg rows (fire-and-forget coalesced stores).
        {
            const float4 z4 = make_float4(0.f, 0.f, 0.f, 0.f);
            #pragma unroll
            for (int i = 0; i < 8; i++) {
                int idx = i * 32 + lane;
                int grow = row0 + warp * 16 + (idx >> 4);
                if (grow < N_NODES)
                    agg4[(size_t)grow * 16 + (idx & 15)] = z4;
            }
        }
        __syncwarp();

        // ---- Pull A fragments: words [8tg, 8tg+8) of own two rows ----
        unsigned w0[8], w1[8];       // [m] = phys cols (16tg+2m, 16tg+2m+1)
        *(uint4*)&w0[0] = *(const uint4*)&Ts[lr0 * TSW + 8 * tg];
        *(uint4*)&w0[4] = *(const uint4*)&Ts[lr0 * TSW + 8 * tg + 4];
        *(uint4*)&w1[0] = *(const uint4*)&Ts[lr1 * TSW + 8 * tg];
        *(uint4*)&w1[4] = *(const uint4*)&Ts[lr1 * TSW + 8 * tg + 4];

        // ================= Layer 1 =================
        float acc[8][4];
        #pragma unroll
        for (int nt = 0; nt < 8; nt++) {
            acc[nt][0] = bh_lo[nt]; acc[nt][1] = bh_hi[nt];
            acc[nt][2] = bh_lo[nt]; acc[nt][3] = bh_hi[nt];
        }
        #pragma unroll
        for (int s = 0; s < 4; s++) {
            unsigned A0 = w0[2 * s],     A1 = w1[2 * s];
            unsigned A2 = w0[2 * s + 1], A3 = w1[2 * s + 1];
            #pragma unroll
            for (int np = 0; np < 4; np++) {
                uint4 b = *(const uint4*)&Wp[((s * 4 + np) * 32 + lane) * 4];
                mma_f16(acc[2 * np],     A0, A1, A2, A3, b.x, b.y);
                mma_f16(acc[2 * np + 1], A0, A1, A2, A3, b.z, b.w);
            }
        }

        // ---- relu + pack: accumulators become layer-2 A fragments ----
        unsigned ha0[4], ha1[4], ha2[4], ha3[4];
        #pragma unroll
        for (int s = 0; s < 4; s++) {
            ha0[s] = h2(fmaxf(acc[2 * s][0], 0.f),     fmaxf(acc[2 * s][1], 0.f));
            ha1[s] = h2(fmaxf(acc[2 * s][2], 0.f),     fmaxf(acc[2 * s][3], 0.f));
            ha2[s] = h2(fmaxf(acc[2 * s + 1][0], 0.f), fmaxf(acc[2 * s + 1][1], 0.f));
            ha3[s] = h2(fmaxf(acc[2 * s + 1][2], 0.f), fmaxf(acc[2 * s + 1][3], 0.f));
        }

        // ================= Layer 2 =================
        #pragma unroll
        for (int nt = 0; nt < 8; nt++) {
            acc[nt][0] = bo_lo[nt]; acc[nt][1] = bo_hi[nt];
            acc[nt][2] = bo_lo[nt]; acc[nt][3] = bo_hi[nt];
        }
        #pragma unroll
        for (int s = 0; s < 4; s++) {
            #pragma unroll
            for (int np = 0; np < 4; np++) {
                uint4 b = *(const uint4*)&Wp[2048 + ((s * 4 + np) * 32 + lane) * 4];
                mma_f16(acc[2 * np],     ha0[s], ha1[s], ha2[s], ha3[s], b.x, b.y);
                mma_f16(acc[2 * np + 1], ha0[s], ha1[s], ha2[s], ha3[s], b.z, b.w);
            }
        }

        // ---- Egress: relu -> own warp stripe as fp32 (warp-private) ----
        __syncwarp();
        #pragma unroll
        for (int nt = 0; nt < 8; nt++) {
            int c = nt * 8 + 2 * tg;
            *(uint2*)&Ts[lr0 * TSW + c] = make_uint2(
                __float_as_uint(fmaxf(acc[nt][0], 0.f)),
                __float_as_uint(fmaxf(acc[nt][1], 0.f)));
            *(uint2*)&Ts[lr1 * TSW + c] = make_uint2(
                __float_as_uint(fmaxf(acc[nt][2], 0.f)),
                __float_as_uint(fmaxf(acc[nt][3], 0.f)));
        }
        __syncwarp();

        // ---- Per-warp coalesced STG.128 of own 16 output rows ----
        #pragma unroll
        for (int i = 0; i < 8; i++) {
            int idx = i * 32 + lane;
            int r  = warp * 16 + (idx >> 4);
            int c4 = idx & 15;
            int grow = row0 + r;
            if (grow < N_NODES) {
                uint4 v = *(const uint4*)&Ts[r * TSW + c4 * 4];
                out4[(size_t)grow * 16 + c4] = make_float4(
                    __uint_as_float(v.x), __uint_as_float(v.y),
                    __uint_as_float(v.z), __uint_as_float(v.w));
            }
        }
        __syncwarp();   // stripe reuse guard before next tile's ingress
    }
}

// ---------------------------------------------------------------------------
// Inputs: 0=X, 1=ref_a, 2=ref_b, 3=v_map(unused), 4=v_count(unused),
//         5=W_hidden, 6=b_hidden, 7=W_out, 8=b_out
// ---------------------------------------------------------------------------
extern "C" void kernel_launch(void* const* d_in, const int* in_sizes, int n_in,
                              void* d_out, int out_size) {
    const float* X   = (const float*)d_in[0];
    const int* ref_a = (const int*)d_in[1];
    const int* ref_b = (const int*)d_in[2];
    const float* Wh  = (const float*)d_in[5];
    const float* bh  = (const float*)d_in[6];
    const float* Wo  = (const float*)d_in[7];
    const float* bo  = (const float*)d_in[8];
    float* out = (float*)d_out;

    float* agg;
    cudaGetSymbolAddress((void**)&agg, g_agg);

    // 1) edge scatter into zeroed agg (zero-invariant maintained by k_mlp)
    {
        long long total = (long long)N_EDGES * 16;
        int blocks = (int)((total + 255) / 256);
        k_scatter<<<blocks, 256>>>((const float4*)X, ref_a, ref_b);
    }

    // 2) persistent FP16 register-fragment MLP
    {
        cudaFuncSetAttribute(k_mlp, cudaFuncAttributeMaxDynamicSharedMemorySize,
                             MLP_SMEM);
        k_mlp<<<GRID_MLP, 256, MLP_SMEM>>>((float4*)agg, (const float4*)X,
                                           Wh, bh, Wo, bo, (float4*)out);
    }
}